// round 1
// baseline (speedup 1.0000x reference)
#include <cuda_runtime.h>

typedef unsigned long long ULL;

// ---- packed f32x2 helpers (Blackwell sm_103a): ptxas never emits FFMA2 from C++ ----
__device__ __forceinline__ ULL f2_pack(float x, float y) {
    ULL r;
    asm("mov.b64 %0, {%1,%2};" : "=l"(r)
        : "r"(__float_as_uint(x)), "r"(__float_as_uint(y)));
    return r;
}
__device__ __forceinline__ void f2_unpack(ULL a, float& x, float& y) {
    unsigned lo, hi;
    asm("mov.b64 {%0,%1}, %2;" : "=r"(lo), "=r"(hi) : "l"(a));
    x = __uint_as_float(lo);
    y = __uint_as_float(hi);
}
__device__ __forceinline__ ULL f2_fma(ULL a, ULL b, ULL c) {
    ULL d;
    asm("fma.rn.f32x2 %0, %1, %2, %3;" : "=l"(d) : "l"(a), "l"(b), "l"(c));
    return d;
}
__device__ __forceinline__ ULL f2_mul(ULL a, ULL b) {
    ULL d;
    asm("mul.rn.f32x2 %0, %1, %2;" : "=l"(d) : "l"(a), "l"(b));
    return d;
}

// ---- problem constants (fixed shapes) ----
constexpr int B = 2, H = 16, S = 4096, D = 64;
constexpr int BH = B * H;
constexpr int WIN = 512;      // sliding window (inclusive of self)
constexpr int GQ = 64;        // global-prefix queries
constexpr int MT = 128;       // queries per banded block
constexpr int CK = 64;        // keys per smem chunk
constexpr float SCALE = 0.125f;   // 1/sqrt(64)
constexpr float NEGV = -1e9f;

constexpr int SPLITS = 16;
constexpr int KPS = S / SPLITS;   // 256 keys per split

// scratch for split-K global prefix (device globals: no allocation allowed)
__device__ float g_pm[BH][SPLITS][GQ];
__device__ float g_pl[BH][SPLITS][GQ];
__device__ float g_pacc[BH][SPLITS][GQ][D];

// =====================================================================
// Kernel 1: banded (sliding-window causal) flash attention.
// One query per lane -> all LDS from K/V smem rows are warp-broadcast.
// =====================================================================
__global__ void __launch_bounds__(MT, 1)
swa_banded(const float* __restrict__ q, const float* __restrict__ k,
           const float* __restrict__ v, float* __restrict__ out) {
    __shared__ float Ks[CK * D];
    __shared__ float Vs[CK * D];

    const int bh = blockIdx.y;
    const int qs = blockIdx.x * MT;
    const int r = threadIdx.x;
    const int i = qs + r;                     // global query position
    const size_t base = (size_t)bh * S * D;

    // q row in registers as 32 f32x2
    ULL qreg[32];
    {
        const float4* qp = (const float4*)(q + base + (size_t)i * D);
#pragma unroll
        for (int t = 0; t < 16; ++t) {
            float4 x = qp[t];
            qreg[2 * t]     = f2_pack(x.x, x.y);
            qreg[2 * t + 1] = f2_pack(x.z, x.w);
        }
    }

    ULL acc[32];
#pragma unroll
    for (int d = 0; d < 32; ++d) acc[d] = 0ULL;
    float m = NEGV, l = 0.f;

    // keys needed: [qs-511, qs+127] -> 10 aligned chunks of 64 from qs-512
#pragma unroll 1
    for (int ch = 0; ch < 10; ++ch) {
        const int j0 = qs - WIN + ch * CK;

        __syncthreads();
        // cooperative load: CK*D floats = 1024 float4 per array, 8 per thread
#pragma unroll
        for (int t = 0; t < 8; ++t) {
            int idx = threadIdx.x + t * MT;   // 0..1023
            int row = idx >> 4;
            int c4 = idx & 15;
            int j = j0 + row;
            float4 kk = make_float4(0.f, 0.f, 0.f, 0.f);
            float4 vv = make_float4(0.f, 0.f, 0.f, 0.f);
            if (j >= 0) {
                kk = *(const float4*)(k + base + (size_t)j * D + c4 * 4);
                vv = *(const float4*)(v + base + (size_t)j * D + c4 * 4);
            }
            *(float4*)(Ks + row * D + c4 * 4) = kk;
            *(float4*)(Vs + row * D + c4 * 4) = vv;
        }
        __syncthreads();

#pragma unroll 1
        for (int gg = 0; gg < CK / 16; ++gg) {
            float s[16];
#pragma unroll
            for (int c = 0; c < 16; ++c) {
                const int kc = gg * 16 + c;
                const ULL* kr = (const ULL*)(Ks + kc * D);
                ULL dp = 0ULL;
#pragma unroll
                for (int d = 0; d < 32; ++d) dp = f2_fma(qreg[d], kr[d], dp);
                float x, y;
                f2_unpack(dp, x, y);
                float sc = (x + y) * SCALE;
                int j = j0 + kc;
                bool valid = (j >= 0) && (j <= i) && (j >= i - (WIN - 1));
                s[c] = valid ? sc : NEGV;
            }
            float mn = m;
#pragma unroll
            for (int c = 0; c < 16; ++c) mn = fmaxf(mn, s[c]);
            if (mn > m) {
                float corr = __expf(m - mn);
                l *= corr;
                ULL c2 = f2_pack(corr, corr);
#pragma unroll
                for (int d = 0; d < 32; ++d) acc[d] = f2_mul(acc[d], c2);
                m = mn;
            }
#pragma unroll
            for (int c = 0; c < 16; ++c) {
                float p = __expf(s[c] - m);
                l += p;
                ULL p2 = f2_pack(p, p);
                const ULL* vr = (const ULL*)(Vs + (gg * 16 + c) * D);
#pragma unroll
                for (int d = 0; d < 32; ++d) acc[d] = f2_fma(p2, vr[d], acc[d]);
            }
        }
    }

    const float inv = 1.f / l;
    float2* op = (float2*)(out + base + (size_t)i * D);
#pragma unroll
    for (int d = 0; d < 32; ++d) {
        float x, y;
        f2_unpack(acc[d], x, y);
        op[d] = make_float2(x * inv, y * inv);
    }
}

// =====================================================================
// Kernel 2: global prefix (first GQ queries attend ALL keys), split-K.
// grid (SPLITS, BH), 64 threads = 64 queries; writes partials.
// =====================================================================
__global__ void __launch_bounds__(GQ, 1)
swa_global(const float* __restrict__ q, const float* __restrict__ k,
           const float* __restrict__ v) {
    __shared__ float Ks[CK * D];
    __shared__ float Vs[CK * D];

    const int bh = blockIdx.y;
    const int sp = blockIdx.x;
    const int qi = threadIdx.x;               // 0..63
    const size_t base = (size_t)bh * S * D;

    ULL qreg[32];
    {
        const float4* qp = (const float4*)(q + base + (size_t)qi * D);
#pragma unroll
        for (int t = 0; t < 16; ++t) {
            float4 x = qp[t];
            qreg[2 * t]     = f2_pack(x.x, x.y);
            qreg[2 * t + 1] = f2_pack(x.z, x.w);
        }
    }
    ULL acc[32];
#pragma unroll
    for (int d = 0; d < 32; ++d) acc[d] = 0ULL;
    float m = NEGV, l = 0.f;

    const int k0 = sp * KPS;
#pragma unroll 1
    for (int ch = 0; ch < KPS / CK; ++ch) {
        const int j0 = k0 + ch * CK;

        __syncthreads();
#pragma unroll
        for (int t = 0; t < 16; ++t) {
            int idx = threadIdx.x + t * GQ;   // 0..1023
            int row = idx >> 4;
            int c4 = idx & 15;
            int j = j0 + row;
            *(float4*)(Ks + row * D + c4 * 4) =
                *(const float4*)(k + base + (size_t)j * D + c4 * 4);
            *(float4*)(Vs + row * D + c4 * 4) =
                *(const float4*)(v + base + (size_t)j * D + c4 * 4);
        }
        __syncthreads();

#pragma unroll 1
        for (int gg = 0; gg < CK / 16; ++gg) {
            float s[16];
#pragma unroll
            for (int c = 0; c < 16; ++c) {
                const int kc = gg * 16 + c;
                const ULL* kr = (const ULL*)(Ks + kc * D);
                ULL dp = 0ULL;
#pragma unroll
                for (int d = 0; d < 32; ++d) dp = f2_fma(qreg[d], kr[d], dp);
                float x, y;
                f2_unpack(dp, x, y);
                s[c] = (x + y) * SCALE;       // no mask: non-causal full attention
            }
            float mn = m;
#pragma unroll
            for (int c = 0; c < 16; ++c) mn = fmaxf(mn, s[c]);
            if (mn > m) {
                float corr = __expf(m - mn);
                l *= corr;
                ULL c2 = f2_pack(corr, corr);
#pragma unroll
                for (int d = 0; d < 32; ++d) acc[d] = f2_mul(acc[d], c2);
                m = mn;
            }
#pragma unroll
            for (int c = 0; c < 16; ++c) {
                float p = __expf(s[c] - m);
                l += p;
                ULL p2 = f2_pack(p, p);
                const ULL* vr = (const ULL*)(Vs + (gg * 16 + c) * D);
#pragma unroll
                for (int d = 0; d < 32; ++d) acc[d] = f2_fma(p2, vr[d], acc[d]);
            }
        }
    }

    g_pm[bh][sp][qi] = m;
    g_pl[bh][sp][qi] = l;
    float2* ap = (float2*)&g_pacc[bh][sp][qi][0];
#pragma unroll
    for (int d = 0; d < 32; ++d) {
        float x, y;
        f2_unpack(acc[d], x, y);
        ap[d] = make_float2(x, y);
    }
}

// =====================================================================
// Kernel 3: combine split-K partials, overwrite rows [0, GQ)
// grid (GQ, BH), D threads
// =====================================================================
__global__ void __launch_bounds__(D, 1)
swa_combine(float* __restrict__ out) {
    const int bh = blockIdx.y;
    const int qi = blockIdx.x;
    const int d = threadIdx.x;

    float M = -1e30f;
#pragma unroll
    for (int s = 0; s < SPLITS; ++s) M = fmaxf(M, g_pm[bh][s][qi]);
    float den = 0.f, num = 0.f;
#pragma unroll
    for (int s = 0; s < SPLITS; ++s) {
        float w = __expf(g_pm[bh][s][qi] - M);
        den += w * g_pl[bh][s][qi];
        num += w * g_pacc[bh][s][qi][d];
    }
    out[(size_t)bh * S * D + (size_t)qi * D + d] = num / den;
}

// =====================================================================
extern "C" void kernel_launch(void* const* d_in, const int* in_sizes, int n_in,
                              void* d_out, int out_size) {
    const float* q = (const float*)d_in[0];
    const float* k = (const float*)d_in[1];
    const float* v = (const float*)d_in[2];
    float* out = (float*)d_out;
    (void)in_sizes; (void)n_in; (void)out_size;

    dim3 g1(S / MT, BH);
    swa_banded<<<g1, MT>>>(q, k, v, out);

    dim3 g2(SPLITS, BH);
    swa_global<<<g2, GQ>>>(q, k, v);

    dim3 g3(GQ, BH);
    swa_combine<<<g3, D>>>(out);
}